// round 4
// baseline (speedup 1.0000x reference)
#include <cuda_runtime.h>
#include <cstdint>

// Problem constants
#define LNUM 2
#define BB   128
#define CIN  64
#define EE   64
#define NHH  8
#define MEM  40
#define HD   8
#define THD  512         // HD*HW
#define PIX  64          // spatial size
#define C_MAIN 192       // CIN + 2E
#define C_PROJ 128       // CIN + E
#define CO_MAIN 320      // 5E
#define CO_PROJ 192      // 3E

#define CHW   120        // padded channel stride in smem (10 rows x 12 cols)
#define SIN_F 7680       // 64 channels * CHW
#define WSTR  100        // per-co weight stride (floats), 100 % 32 = 4 -> conflict-free
#define WT_F  (64 * WSTR)
#define CONV_SMEM ((SIN_F + WT_F) * 4)

// ---------------- scratch (device globals; no allocation) ----------------
__device__ float g_inp  [BB * C_MAIN * PIX];   // (B,192,64)
__device__ float g_gates[BB * CO_MAIN * PIX];  // (B,320,64)
__device__ float g_kqv  [BB * CO_PROJ * PIX];  // (B,192,64)
__device__ float g_attn [BB * EE * PIX];       // (B,64,64)
__device__ float g_out  [BB * EE * PIX];       // (B,64,64)
__device__ float g_bias [BB * MEM];
__device__ float g_nd   [BB];
__device__ int   g_is_i32;

__device__ __forceinline__ float sigmoidf_(float v) {
    return 1.0f / (1.0f + __expf(-v));
}

// ---------------- dtype detection for bool inputs ----------------
__global__ void detect_kernel(const int* __restrict__ sm) {
    if (threadIdx.x != 0 || blockIdx.x != 0) return;
    int ok = 1;
    for (int i = 0; i < (BB * MEM) / 4; i++) {
        int v = sm[i];
        if (v != 0 && v != 1) { ok = 0; break; }
    }
    g_is_i32 = ok;
}

__device__ __forceinline__ int read_bool(const void* p, int idx) {
    if (g_is_i32) return ((const int*)p)[idx] != 0;
    return ((const unsigned char*)p)[idx] != 0;
}

// ---------------- bias + notdone ----------------
__global__ void bias_kernel(const void* __restrict__ src_mask,
                            const void* __restrict__ notdone) {
    int t = blockIdx.x * 256 + threadIdx.x;
    if (t < BB) g_nd[t] = read_bool(notdone, t) ? 1.0f : 0.0f;
    if (t >= BB * MEM) return;
    int b = t / MEM, m = t - b * MEM;
    float v;
    if (m == MEM - 1) {
        v = 3.0f;  // MASK_B
    } else {
        bool masked = read_bool(src_mask, b * MEM + m + 1) || !read_bool(notdone, b);
        v = masked ? -1e9f : 0.0f;
    }
    g_bias[t] = v;
}

// ---------------- build concat input (x | out | h*nd) ----------------
__global__ void prep_kernel(const float* __restrict__ x,
                            const float* __restrict__ h0,
                            int n, int first) {
    int idx = blockIdx.x * 256 + threadIdx.x;
    if (idx >= BB * C_MAIN * PIX) return;
    int b = idx / (C_MAIN * PIX);
    int r = idx - b * (C_MAIN * PIX);
    int c = r >> 6;
    int p = r & 63;
    float nd = g_nd[b];
    float v;
    if (c < CIN) {
        v = x[b * (CIN * PIX) + r];
    } else if (c < CIN + EE) {
        int off = b * (EE * PIX) + (c - CIN) * PIX + p;
        if (first)
            v = h0[((size_t)(LNUM - 1) * BB + b) * (EE * PIX) + (c - CIN) * PIX + p] * nd;
        else
            v = g_out[off];
    } else {
        v = h0[((size_t)n * BB + b) * (EE * PIX) + (c - CIN - EE) * PIX + p] * nd;
    }
    g_inp[idx] = v;
}

// ---------------- fused main(192->320) + proj(128->192) 3x3 SAME conv ----
// grid = (B, 8): y<5 -> main co [64y,...), y>=5 -> proj co [64(y-5),...)
// 128 threads: thread (row = tid&7, cg = tid>>3 in 0..15) computes
// co = cobase + cg + {0,16,32,48} over 8 pixels of its row, sharing one
// 3x10 register input neighborhood across all 4 output channels.
__global__ void __launch_bounds__(128, 3)
conv_fused_kernel(const float* __restrict__ main_w,
                  const float* __restrict__ main_b,
                  const float* __restrict__ proj_w,
                  const float* __restrict__ proj_b,
                  int n) {
    extern __shared__ float smem[];
    float* sin = smem;          // SIN_F: 64ch x (10 rows x 12 cols)
    float* wt  = smem + SIN_F;  // WT_F:  64co x WSTR (8cc x 12 used)

    int b = blockIdx.x;
    int y = blockIdx.y;
    bool ismain = (y < 5);
    int cobase = ismain ? y * 64 : (y - 5) * 64;
    int cin    = ismain ? C_MAIN : C_PROJ;
    int nchunk = cin >> 6;
    const float* wsrc = ismain
        ? main_w + (size_t)n * CO_MAIN * C_MAIN * 9
        : proj_w + (size_t)n * CO_PROJ * C_PROJ * 9;
    const float* inp = g_inp + (size_t)b * C_MAIN * PIX;

    int tid = threadIdx.x;
    int row = tid & 7;
    int cg  = tid >> 3;      // 0..15
    int co_l = tid >> 1;     // staging: 2 threads per co
    int half = tid & 1;

    float acc[4][8];
#pragma unroll
    for (int c4 = 0; c4 < 4; c4++)
#pragma unroll
        for (int xx = 0; xx < 8; xx++) acc[c4][xx] = 0.0f;

    // zero input smem once (padding stays 0; interior overwritten per chunk)
    for (int i = tid; i < SIN_F; i += 128) sin[i] = 0.0f;

    for (int chunk = 0; chunk < nchunk; chunk++) {
        int c0 = chunk * 64;
        __syncthreads();   // previous compute done before refill
        for (int i = tid; i < 64 * PIX; i += 128) {
            int ch = i >> 6, p = i & 63;
            sin[ch * CHW + ((p >> 3) + 1) * 12 + (p & 7) + 1] = inp[(c0 + ch) * PIX + p];
        }
        for (int cs = 0; cs < 64; cs += 8) {
            __syncthreads();
            {
                // stage weights: co_l's cc in [half*4, half*4+4)
                const float* src = wsrc + (size_t)(cobase + co_l) * cin * 9
                                        + (c0 + cs + half * 4) * 9;
                float* dst = wt + co_l * WSTR + half * 48;
#pragma unroll
                for (int j = 0; j < 4; j++)
#pragma unroll
                    for (int k = 0; k < 9; k++) dst[j * 12 + k] = src[j * 9 + k];
            }
            __syncthreads();
#pragma unroll
            for (int cc = 0; cc < 8; cc++) {
                const float* s = sin + (cs + cc) * CHW + row * 12;
                float rv[30];
                *(float4*)(rv + 0)  = *(const float4*)(s + 0);
                *(float4*)(rv + 4)  = *(const float4*)(s + 4);
                *(float2*)(rv + 8)  = *(const float2*)(s + 8);
                *(float4*)(rv + 10) = *(const float4*)(s + 12);
                *(float4*)(rv + 14) = *(const float4*)(s + 16);
                *(float2*)(rv + 18) = *(const float2*)(s + 20);
                *(float4*)(rv + 20) = *(const float4*)(s + 24);
                *(float4*)(rv + 24) = *(const float4*)(s + 28);
                *(float2*)(rv + 28) = *(const float2*)(s + 32);
#pragma unroll
                for (int c4 = 0; c4 < 4; c4++) {
                    const float4* wv = (const float4*)(wt + (cg + 16 * c4) * WSTR + cc * 12);
                    float4 wA = wv[0];
                    float4 wB = wv[1];
                    float4 wC = wv[2];
                    float w[9] = { wA.x, wA.y, wA.z, wA.w,
                                   wB.x, wB.y, wB.z, wB.w, wC.x };
#pragma unroll
                    for (int r = 0; r < 3; r++) {
#pragma unroll
                        for (int kk = 0; kk < 3; kk++) {
                            float f = w[r * 3 + kk];
#pragma unroll
                            for (int xx = 0; xx < 8; xx++)
                                acc[c4][xx] = fmaf(rv[r * 10 + xx + kk], f, acc[c4][xx]);
                        }
                    }
                }
            }
        }
    }

#pragma unroll
    for (int c4 = 0; c4 < 4; c4++) {
        int co = cobase + cg + 16 * c4;
        if (ismain) {
            float bb = main_b[n * CO_MAIN + co];
            float* o = g_gates + ((size_t)b * CO_MAIN + co) * PIX + row * 8;
#pragma unroll
            for (int xx = 0; xx < 8; xx++) o[xx] = acc[c4][xx] + bb;
        } else {
            float bb = proj_b[n * CO_PROJ + co];
            float* o = g_kqv + ((size_t)b * CO_PROJ + co) * PIX + row * 8;
#pragma unroll
            for (int xx = 0; xx < 8; xx++) o[xx] = acc[c4][xx] + bb;
        }
    }
}

// ---------------- attention over rolling memory ----------------
__global__ void attn_kernel(const float* __restrict__ k0,
                            const float* __restrict__ v0,
                            const float* __restrict__ pos_w,
                            const float* __restrict__ pos_b,
                            int n) {
    int b = blockIdx.x;
    int h = blockIdx.y;
    int tid = threadIdx.x;
    __shared__ float q[THD], kn[THD], vn[THD];
    __shared__ float sc[MEM], wts[MEM];

    const float* kqv = g_kqv + (size_t)b * CO_PROJ * PIX;
    const float rscale = 0.044194173824159216f;  // 1/sqrt(512)
    for (int d = tid; d < THD; d += 256) {
        int hd = d >> 6, hw = d & 63;
        kn[d] = kqv[(h * 24 + hd) * PIX + hw];
        q[d]  = kqv[(h * 24 + 8 + hd) * PIX + hw] * rscale;
        vn[d] = kqv[(h * 24 + 16 + hd) * PIX + hw];
    }
    __syncthreads();

    const float* kb  = k0 + ((((size_t)n * BB + b) * NHH + h) * MEM) * THD;
    const float* pwb = pos_w + (size_t)n * MEM * (NHH * THD) + h * THD;
    int warp = tid >> 5, lane = tid & 31;
    for (int m = warp; m < MEM; m += 8) {
        const float* kr = (m < MEM - 1) ? (kb + (size_t)(m + 1) * THD) : kn;
        const float* pr = pwb + (size_t)m * (NHH * THD);
        float p = 0.0f;
        for (int d = lane; d < THD; d += 32)
            p = fmaf(q[d], kr[d] + pr[d], p);
#pragma unroll
        for (int o = 16; o; o >>= 1) p += __shfl_xor_sync(0xffffffffu, p, o);
        if (lane == 0)
            sc[m] = p + g_bias[b * MEM + m] + pos_b[(size_t)n * MEM * NHH + m * NHH + h];
    }
    __syncthreads();
    if (tid == 0) {
        float mx = sc[0];
#pragma unroll
        for (int m = 1; m < MEM; m++) mx = fmaxf(mx, sc[m]);
        float s = 0.0f;
#pragma unroll
        for (int m = 0; m < MEM; m++) {
            float e = __expf(sc[m] - mx);
            wts[m] = e;
            s += e;
        }
        float inv = 1.0f / s;
#pragma unroll
        for (int m = 0; m < MEM; m++) wts[m] *= inv;
    }
    __syncthreads();

    const float* vb = v0 + ((((size_t)n * BB + b) * NHH + h) * MEM) * THD;
    for (int d = tid; d < THD; d += 256) {
        float acc = wts[MEM - 1] * vn[d];
        for (int m = 0; m < MEM - 1; m++)
            acc = fmaf(wts[m], vb[(size_t)(m + 1) * THD + d], acc);
        int hd = d >> 6, hw = d & 63;
        g_attn[(size_t)b * (EE * PIX) + (h * 8 + hd) * PIX + hw] = acc;
    }
}

// ---------------- out conv + residual + layernorm + LSTM combine ---------
__global__ void final_kernel(const float* __restrict__ out_w,
                             const float* __restrict__ out_b,
                             const float* __restrict__ ln_w,
                             const float* __restrict__ ln_b,
                             const float* __restrict__ c0,
                             const float* __restrict__ x,
                             int n, float* __restrict__ dst_last, int last) {
    __shared__ float sa[EE * 100];   // padded attn input
    __shared__ float ao[EE * PIX];   // conv+residual result
    __shared__ float red[16];
    __shared__ float s_mu, s_rv;
    int b = blockIdx.x;
    int tid = threadIdx.x;

    for (int i = tid; i < EE * 100; i += 256) sa[i] = 0.0f;
    __syncthreads();
    const float* at = g_attn + (size_t)b * EE * PIX;
    for (int i = tid; i < EE * PIX; i += 256) {
        int c = i >> 6, p = i & 63;
        sa[c * 100 + ((p >> 3) + 1) * 10 + (p & 7) + 1] = at[i];
    }
    __syncthreads();

    const float* wb = out_w + (size_t)n * EE * EE * 9;
    const float* xr = x + (size_t)b * EE * PIX;
    for (int t = tid; t < EE * 8; t += 256) {
        int co = t >> 3;
        int row = t & 7;
        const float* wc = wb + (size_t)co * EE * 9;
        float acc[8];
#pragma unroll
        for (int xx = 0; xx < 8; xx++) acc[xx] = 0.0f;
        for (int c = 0; c < EE; c++) {
            const float* s = sa + c * 100 + row * 10;
            const float* w = wc + c * 9;
            float w0 = w[0], w1 = w[1], w2 = w[2];
            float w3 = w[3], w4 = w[4], w5 = w[5];
            float w6 = w[6], w7 = w[7], w8 = w[8];
#pragma unroll
            for (int xx = 0; xx < 8; xx++) {
                float a = acc[xx];
                a = fmaf(s[xx],      w0, a);
                a = fmaf(s[xx + 1],  w1, a);
                a = fmaf(s[xx + 2],  w2, a);
                a = fmaf(s[10 + xx],     w3, a);
                a = fmaf(s[10 + xx + 1], w4, a);
                a = fmaf(s[10 + xx + 2], w5, a);
                a = fmaf(s[20 + xx],     w6, a);
                a = fmaf(s[20 + xx + 1], w7, a);
                a = fmaf(s[20 + xx + 2], w8, a);
                acc[xx] = a;
            }
        }
        float bb = out_b[n * EE + co];
        int base = co * PIX + row * 8;
#pragma unroll
        for (int xx = 0; xx < 8; xx++)
            ao[base + xx] = acc[xx] + bb + xr[base + xx];
    }
    __syncthreads();

    float s1 = 0.0f, s2 = 0.0f;
    for (int i = tid; i < EE * PIX; i += 256) {
        float v = ao[i];
        s1 += v;
        s2 += v * v;
    }
    int warp = tid >> 5, lane = tid & 31;
#pragma unroll
    for (int o = 16; o; o >>= 1) {
        s1 += __shfl_xor_sync(0xffffffffu, s1, o);
        s2 += __shfl_xor_sync(0xffffffffu, s2, o);
    }
    if (lane == 0) { red[warp] = s1; red[8 + warp] = s2; }
    __syncthreads();
    if (tid == 0) {
        float a = 0.0f, q2 = 0.0f;
#pragma unroll
        for (int w2 = 0; w2 < 8; w2++) { a += red[w2]; q2 += red[8 + w2]; }
        float mu = a * (1.0f / 4096.0f);
        float var = q2 * (1.0f / 4096.0f) - mu * mu;
        s_mu = mu;
        s_rv = rsqrtf(var + 1e-5f);
    }
    __syncthreads();
    float mu = s_mu, rv = s_rv;

    const float* gb = g_gates + (size_t)b * CO_MAIN * PIX;
    const float* cb = c0 + ((size_t)n * BB + b) * (EE * PIX);
    float nd = g_nd[b];
    float* dst = (last ? dst_last : g_out) + (size_t)b * EE * PIX;
    const float* lw = ln_w + (size_t)n * EE * PIX;
    const float* lb = ln_b + (size_t)n * EE * PIX;
    for (int i = tid; i < EE * PIX; i += 256) {
        int c = i >> 6, p = i & 63;
        float aon = (ao[i] - mu) * rv * lw[i] + lb[i];
        float gi = sigmoidf_(gb[(0 * EE + c) * PIX + p]);
        float gf = sigmoidf_(gb[(1 * EE + c) * PIX + p]);
        float go = sigmoidf_(gb[(2 * EE + c) * PIX + p]);
        float gg = tanhf(gb[(3 * EE + c) * PIX + p]);
        float ga = sigmoidf_(gb[(4 * EE + c) * PIX + p]);
        float cn = gf * (cb[i] * nd) + gi * gg + ga * tanhf(aon);
        dst[i] = go * tanhf(cn);
    }
}

// ---------------- launch ----------------
extern "C" void kernel_launch(void* const* d_in, const int* in_sizes, int n_in,
                              void* d_out, int out_size) {
    const float* x       = (const float*)d_in[0];
    const float* h0      = (const float*)d_in[1];
    const float* c0      = (const float*)d_in[2];
    const float* k0      = (const float*)d_in[3];
    const float* v0      = (const float*)d_in[4];
    const void*  src_mask = d_in[5];
    const void*  notdone  = d_in[6];
    const float* main_w  = (const float*)d_in[7];
    const float* main_b  = (const float*)d_in[8];
    const float* proj_w  = (const float*)d_in[9];
    const float* proj_b  = (const float*)d_in[10];
    const float* out_w   = (const float*)d_in[11];
    const float* out_b   = (const float*)d_in[12];
    const float* ln_w    = (const float*)d_in[13];
    const float* ln_b    = (const float*)d_in[14];
    const float* pos_w   = (const float*)d_in[15];
    const float* pos_b   = (const float*)d_in[16];
    float* out = (float*)d_out;

    cudaFuncSetAttribute(conv_fused_kernel,
                         cudaFuncAttributeMaxDynamicSharedMemorySize, CONV_SMEM);

    detect_kernel<<<1, 1>>>((const int*)src_mask);
    bias_kernel<<<(BB * MEM + 255) / 256, 256>>>(src_mask, notdone);
    for (int n = 0; n < LNUM; n++) {
        int tot = BB * C_MAIN * PIX;
        prep_kernel<<<(tot + 255) / 256, 256>>>(x, h0, n, n == 0 ? 1 : 0);
        conv_fused_kernel<<<dim3(BB, 8), 128, CONV_SMEM>>>(main_w, main_b,
                                                           proj_w, proj_b, n);
        attn_kernel<<<dim3(BB, NHH), 256>>>(k0, v0, pos_w, pos_b, n);
        final_kernel<<<BB, 256>>>(out_w, out_b, ln_w, ln_b, c0, x, n,
                                  out, n == LNUM - 1 ? 1 : 0);
    }
}

// round 5
// speedup vs baseline: 1.1967x; 1.1967x over previous
#include <cuda_runtime.h>
#include <cstdint>

// Problem constants
#define LNUM 2
#define BB   128
#define CIN  64
#define EE   64
#define NHH  8
#define MEM  40
#define HD   8
#define THD  512         // HD*HW
#define PIX  64          // spatial size
#define C_MAIN 192       // CIN + 2E
#define C_PROJ 128       // CIN + E
#define CO_MAIN 320      // 5E
#define CO_PROJ 192      // 3E

#define CHW   120        // padded channel stride in smem (10 rows x 12 cols)
#define SIN_F 7680       // 64 channels * CHW
#define WSTR  100        // per-co weight stride (floats); 100 mod 32 = 4 -> conflict-free
#define WT_F  (64 * WSTR)
#define CONV_SMEM ((SIN_F + WT_F) * 4)   // 56.3 KB

// ---------------- scratch (device globals; no allocation) ----------------
__device__ float g_inp  [BB * C_MAIN * PIX];   // (B,192,64)
__device__ float g_gates[BB * CO_MAIN * PIX];  // (B,320,64)
__device__ float g_kqv  [BB * CO_PROJ * PIX];  // (B,192,64)
__device__ float g_attn [BB * EE * PIX];       // (B,64,64)
__device__ float g_out  [BB * EE * PIX];       // (B,64,64)
__device__ float g_bias [BB * MEM];
__device__ float g_nd   [BB];
__device__ int   g_is_i32;

__device__ __forceinline__ float sigmoidf_(float v) {
    return 1.0f / (1.0f + __expf(-v));
}

// ---------------- dtype detection for bool inputs (parallel) ----------------
__global__ void detect_kernel(const int* __restrict__ sm) {
    __shared__ int bad;
    if (threadIdx.x == 0) bad = 0;
    __syncthreads();
    int anybad = 0;
    for (int i = threadIdx.x; i < (BB * MEM) / 4; i += 256) {
        int v = sm[i];
        if (v != 0 && v != 1) anybad = 1;
    }
    if (anybad) bad = 1;
    __syncthreads();
    if (threadIdx.x == 0) g_is_i32 = !bad;
}

__device__ __forceinline__ int read_bool(const void* p, int idx) {
    if (g_is_i32) return ((const int*)p)[idx] != 0;
    return ((const unsigned char*)p)[idx] != 0;
}

// ---------------- bias + notdone ----------------
__global__ void bias_kernel(const void* __restrict__ src_mask,
                            const void* __restrict__ notdone) {
    int t = blockIdx.x * 256 + threadIdx.x;
    if (t < BB) g_nd[t] = read_bool(notdone, t) ? 1.0f : 0.0f;
    if (t >= BB * MEM) return;
    int b = t / MEM, m = t - b * MEM;
    float v;
    if (m == MEM - 1) {
        v = 3.0f;  // MASK_B
    } else {
        bool masked = read_bool(src_mask, b * MEM + m + 1) || !read_bool(notdone, b);
        v = masked ? -1e9f : 0.0f;
    }
    g_bias[t] = v;
}

// ---------------- build concat input (x | out | h*nd) ----------------
__global__ void prep_kernel(const float* __restrict__ x,
                            const float* __restrict__ h0,
                            int n, int first) {
    int idx = blockIdx.x * 256 + threadIdx.x;
    if (idx >= BB * C_MAIN * PIX) return;
    int b = idx / (C_MAIN * PIX);
    int r = idx - b * (C_MAIN * PIX);
    int c = r >> 6;
    int p = r & 63;
    float nd = g_nd[b];
    float v;
    if (c < CIN) {
        v = x[b * (CIN * PIX) + r];
    } else if (c < CIN + EE) {
        int off = b * (EE * PIX) + (c - CIN) * PIX + p;
        if (first)
            v = h0[((size_t)(LNUM - 1) * BB + b) * (EE * PIX) + (c - CIN) * PIX + p] * nd;
        else
            v = g_out[off];
    } else {
        v = h0[((size_t)n * BB + b) * (EE * PIX) + (c - CIN - EE) * PIX + p] * nd;
    }
    g_inp[idx] = v;
}

// ---------------- fused main(192->320) + proj(128->192) 3x3 SAME conv ----
// grid = (B, 8): y<5 -> main co [64y,...), y>=5 -> proj co [64(y-5),...)
// 256 threads: thread (row = tid&7, cog = tid>>3 in 0..31) computes
// co = cobase + cog and co = cobase + cog + 32 over 8 pixels of its row,
// sharing one 3x10 register input neighborhood across both channels.
// Weights staged in padded smem (stride WSTR=100, 12 floats per cc) and
// read via 3x LDS.128 per (co,cc): conflict-free.
__global__ void __launch_bounds__(256, 2)
conv_fused_kernel(const float* __restrict__ main_w,
                  const float* __restrict__ main_b,
                  const float* __restrict__ proj_w,
                  const float* __restrict__ proj_b,
                  int n) {
    extern __shared__ float smem[];
    float* sin = smem;          // SIN_F: 64ch x (10 rows x 12 cols)
    float* wt  = smem + SIN_F;  // WT_F:  64co x WSTR (8 cc x 12 floats used)

    int b = blockIdx.x;
    int y = blockIdx.y;
    bool ismain = (y < 5);
    int cobase = ismain ? y * 64 : (y - 5) * 64;
    int cin    = ismain ? C_MAIN : C_PROJ;
    int nchunk = cin >> 6;
    const float* wsrc = ismain
        ? main_w + (size_t)n * CO_MAIN * C_MAIN * 9
        : proj_w + (size_t)n * CO_PROJ * C_PROJ * 9;
    const float* inp = g_inp + (size_t)b * C_MAIN * PIX;

    int tid = threadIdx.x;
    int row = tid & 7;
    int cog = tid >> 3;       // 0..31
    int co_s = tid >> 2;      // staging: 4 threads per co
    int part = tid & 3;       // each part covers cc = 2*part, 2*part+1

    float acc0[8], acc1[8];
#pragma unroll
    for (int xx = 0; xx < 8; xx++) { acc0[xx] = 0.0f; acc1[xx] = 0.0f; }

    // zero input smem once (padding stays 0; interior overwritten per chunk)
    for (int i = tid; i < SIN_F; i += 256) sin[i] = 0.0f;

    for (int chunk = 0; chunk < nchunk; chunk++) {
        int c0 = chunk * 64;
        __syncthreads();   // previous compute done before refill
        for (int i = tid; i < 64 * PIX; i += 256) {
            int ch = i >> 6, p = i & 63;
            sin[ch * CHW + ((p >> 3) + 1) * 12 + (p & 7) + 1] = inp[(c0 + ch) * PIX + p];
        }
        for (int cs = 0; cs < 64; cs += 8) {
            __syncthreads();   // prior compute done / input ready
            {
                // stage 18 contiguous weights (2 cc) per thread into padded rows
                const float* src = wsrc + (size_t)(cobase + co_s) * cin * 9
                                        + (c0 + cs + 2 * part) * 9;
                float* dst = wt + co_s * WSTR + (2 * part) * 12;
#pragma unroll
                for (int k = 0; k < 9; k++) dst[k] = src[k];
#pragma unroll
                for (int k = 0; k < 9; k++) dst[12 + k] = src[9 + k];
            }
            __syncthreads();
#pragma unroll
            for (int cc = 0; cc < 8; cc++) {
                const float* s = sin + (cs + cc) * CHW + row * 12;
                float rv[30];
                *(float4*)(rv + 0)  = *(const float4*)(s + 0);
                *(float4*)(rv + 4)  = *(const float4*)(s + 4);
                *(float2*)(rv + 8)  = *(const float2*)(s + 8);
                *(float4*)(rv + 10) = *(const float4*)(s + 12);
                *(float4*)(rv + 14) = *(const float4*)(s + 16);
                *(float2*)(rv + 18) = *(const float2*)(s + 20);
                *(float4*)(rv + 20) = *(const float4*)(s + 24);
                *(float4*)(rv + 24) = *(const float4*)(s + 28);
                *(float2*)(rv + 28) = *(const float2*)(s + 32);

                const float4* wv0 = (const float4*)(wt + cog * WSTR + cc * 12);
                const float4* wv1 = (const float4*)(wt + (cog + 32) * WSTR + cc * 12);
                float4 a0 = wv0[0], a1 = wv0[1], a2 = wv0[2];
                float4 b0 = wv1[0], b1 = wv1[1], b2 = wv1[2];
                float wa[9] = { a0.x, a0.y, a0.z, a0.w, a1.x, a1.y, a1.z, a1.w, a2.x };
                float wb[9] = { b0.x, b0.y, b0.z, b0.w, b1.x, b1.y, b1.z, b1.w, b2.x };
#pragma unroll
                for (int r = 0; r < 3; r++) {
#pragma unroll
                    for (int kk = 0; kk < 3; kk++) {
                        float fa = wa[r * 3 + kk];
                        float fb = wb[r * 3 + kk];
#pragma unroll
                        for (int xx = 0; xx < 8; xx++) {
                            acc0[xx] = fmaf(rv[r * 10 + xx + kk], fa, acc0[xx]);
                            acc1[xx] = fmaf(rv[r * 10 + xx + kk], fb, acc1[xx]);
                        }
                    }
                }
            }
        }
    }

    int co0 = cobase + cog;
    int co1 = cobase + cog + 32;
    if (ismain) {
        float b0 = main_b[n * CO_MAIN + co0];
        float b1 = main_b[n * CO_MAIN + co1];
        float* o0 = g_gates + ((size_t)b * CO_MAIN + co0) * PIX + row * 8;
        float* o1 = g_gates + ((size_t)b * CO_MAIN + co1) * PIX + row * 8;
#pragma unroll
        for (int xx = 0; xx < 8; xx++) { o0[xx] = acc0[xx] + b0; o1[xx] = acc1[xx] + b1; }
    } else {
        float b0 = proj_b[n * CO_PROJ + co0];
        float b1 = proj_b[n * CO_PROJ + co1];
        float* o0 = g_kqv + ((size_t)b * CO_PROJ + co0) * PIX + row * 8;
        float* o1 = g_kqv + ((size_t)b * CO_PROJ + co1) * PIX + row * 8;
#pragma unroll
        for (int xx = 0; xx < 8; xx++) { o0[xx] = acc0[xx] + b0; o1[xx] = acc1[xx] + b1; }
    }
}

// ---------------- attention over rolling memory ----------------
__global__ void attn_kernel(const float* __restrict__ k0,
                            const float* __restrict__ v0,
                            const float* __restrict__ pos_w,
                            const float* __restrict__ pos_b,
                            int n) {
    int b = blockIdx.x;
    int h = blockIdx.y;
    int tid = threadIdx.x;
    __shared__ float q[THD], kn[THD], vn[THD];
    __shared__ float sc[MEM], wts[MEM];

    const float* kqv = g_kqv + (size_t)b * CO_PROJ * PIX;
    const float rscale = 0.044194173824159216f;  // 1/sqrt(512)
    for (int d = tid; d < THD; d += 256) {
        int hd = d >> 6, hw = d & 63;
        kn[d] = kqv[(h * 24 + hd) * PIX + hw];
        q[d]  = kqv[(h * 24 + 8 + hd) * PIX + hw] * rscale;
        vn[d] = kqv[(h * 24 + 16 + hd) * PIX + hw];
    }
    __syncthreads();

    const float* kb  = k0 + ((((size_t)n * BB + b) * NHH + h) * MEM) * THD;
    const float* pwb = pos_w + (size_t)n * MEM * (NHH * THD) + h * THD;
    int warp = tid >> 5, lane = tid & 31;
    for (int m = warp; m < MEM; m += 8) {
        const float* kr = (m < MEM - 1) ? (kb + (size_t)(m + 1) * THD) : kn;
        const float* pr = pwb + (size_t)m * (NHH * THD);
        float p = 0.0f;
        for (int d = lane; d < THD; d += 32)
            p = fmaf(q[d], kr[d] + pr[d], p);
#pragma unroll
        for (int o = 16; o; o >>= 1) p += __shfl_xor_sync(0xffffffffu, p, o);
        if (lane == 0)
            sc[m] = p + g_bias[b * MEM + m] + pos_b[(size_t)n * MEM * NHH + m * NHH + h];
    }
    __syncthreads();
    if (tid == 0) {
        float mx = sc[0];
#pragma unroll
        for (int m = 1; m < MEM; m++) mx = fmaxf(mx, sc[m]);
        float s = 0.0f;
#pragma unroll
        for (int m = 0; m < MEM; m++) {
            float e = __expf(sc[m] - mx);
            wts[m] = e;
            s += e;
        }
        float inv = 1.0f / s;
#pragma unroll
        for (int m = 0; m < MEM; m++) wts[m] *= inv;
    }
    __syncthreads();

    const float* vb = v0 + ((((size_t)n * BB + b) * NHH + h) * MEM) * THD;
    for (int d = tid; d < THD; d += 256) {
        float acc = wts[MEM - 1] * vn[d];
        for (int m = 0; m < MEM - 1; m++)
            acc = fmaf(wts[m], vb[(size_t)(m + 1) * THD + d], acc);
        int hd = d >> 6, hw = d & 63;
        g_attn[(size_t)b * (EE * PIX) + (h * 8 + hd) * PIX + hw] = acc;
    }
}

// ---------------- out conv + residual + layernorm + LSTM combine ---------
__global__ void final_kernel(const float* __restrict__ out_w,
                             const float* __restrict__ out_b,
                             const float* __restrict__ ln_w,
                             const float* __restrict__ ln_b,
                             const float* __restrict__ c0,
                             const float* __restrict__ x,
                             int n, float* __restrict__ dst_last, int last) {
    __shared__ float sa[EE * 100];   // padded attn input
    __shared__ float ao[EE * PIX];   // conv+residual result
    __shared__ float red[16];
    __shared__ float s_mu, s_rv;
    int b = blockIdx.x;
    int tid = threadIdx.x;

    for (int i = tid; i < EE * 100; i += 256) sa[i] = 0.0f;
    __syncthreads();
    const float* at = g_attn + (size_t)b * EE * PIX;
    for (int i = tid; i < EE * PIX; i += 256) {
        int c = i >> 6, p = i & 63;
        sa[c * 100 + ((p >> 3) + 1) * 10 + (p & 7) + 1] = at[i];
    }
    __syncthreads();

    const float* wb = out_w + (size_t)n * EE * EE * 9;
    const float* xr = x + (size_t)b * EE * PIX;
    for (int t = tid; t < EE * 8; t += 256) {
        int co = t >> 3;
        int row = t & 7;
        const float* wc = wb + (size_t)co * EE * 9;
        float acc[8];
#pragma unroll
        for (int xx = 0; xx < 8; xx++) acc[xx] = 0.0f;
        for (int c = 0; c < EE; c++) {
            const float* s = sa + c * 100 + row * 10;
            const float* w = wc + c * 9;
            float w0 = w[0], w1 = w[1], w2 = w[2];
            float w3 = w[3], w4 = w[4], w5 = w[5];
            float w6 = w[6], w7 = w[7], w8 = w[8];
#pragma unroll
            for (int xx = 0; xx < 8; xx++) {
                float a = acc[xx];
                a = fmaf(s[xx],      w0, a);
                a = fmaf(s[xx + 1],  w1, a);
                a = fmaf(s[xx + 2],  w2, a);
                a = fmaf(s[10 + xx],     w3, a);
                a = fmaf(s[10 + xx + 1], w4, a);
                a = fmaf(s[10 + xx + 2], w5, a);
                a = fmaf(s[20 + xx],     w6, a);
                a = fmaf(s[20 + xx + 1], w7, a);
                a = fmaf(s[20 + xx + 2], w8, a);
                acc[xx] = a;
            }
        }
        float bb = out_b[n * EE + co];
        int base = co * PIX + row * 8;
#pragma unroll
        for (int xx = 0; xx < 8; xx++)
            ao[base + xx] = acc[xx] + bb + xr[base + xx];
    }
    __syncthreads();

    float s1 = 0.0f, s2 = 0.0f;
    for (int i = tid; i < EE * PIX; i += 256) {
        float v = ao[i];
        s1 += v;
        s2 += v * v;
    }
    int warp = tid >> 5, lane = tid & 31;
#pragma unroll
    for (int o = 16; o; o >>= 1) {
        s1 += __shfl_xor_sync(0xffffffffu, s1, o);
        s2 += __shfl_xor_sync(0xffffffffu, s2, o);
    }
    if (lane == 0) { red[warp] = s1; red[8 + warp] = s2; }
    __syncthreads();
    if (tid == 0) {
        float a = 0.0f, q2 = 0.0f;
#pragma unroll
        for (int w2 = 0; w2 < 8; w2++) { a += red[w2]; q2 += red[8 + w2]; }
        float mu = a * (1.0f / 4096.0f);
        float var = q2 * (1.0f / 4096.0f) - mu * mu;
        s_mu = mu;
        s_rv = rsqrtf(var + 1e-5f);
    }
    __syncthreads();
    float mu = s_mu, rv = s_rv;

    const float* gb = g_gates + (size_t)b * CO_MAIN * PIX;
    const float* cb = c0 + ((size_t)n * BB + b) * (EE * PIX);
    float nd = g_nd[b];
    float* dst = (last ? dst_last : g_out) + (size_t)b * EE * PIX;
    const float* lw = ln_w + (size_t)n * EE * PIX;
    const float* lb = ln_b + (size_t)n * EE * PIX;
    for (int i = tid; i < EE * PIX; i += 256) {
        int c = i >> 6, p = i & 63;
        float aon = (ao[i] - mu) * rv * lw[i] + lb[i];
        float gi = sigmoidf_(gb[(0 * EE + c) * PIX + p]);
        float gf = sigmoidf_(gb[(1 * EE + c) * PIX + p]);
        float go = sigmoidf_(gb[(2 * EE + c) * PIX + p]);
        float gg = tanhf(gb[(3 * EE + c) * PIX + p]);
        float ga = sigmoidf_(gb[(4 * EE + c) * PIX + p]);
        float cn = gf * (cb[i] * nd) + gi * gg + ga * tanhf(aon);
        dst[i] = go * tanhf(cn);
    }
}

// ---------------- launch ----------------
extern "C" void kernel_launch(void* const* d_in, const int* in_sizes, int n_in,
                              void* d_out, int out_size) {
    const float* x       = (const float*)d_in[0];
    const float* h0      = (const float*)d_in[1];
    const float* c0      = (const float*)d_in[2];
    const float* k0      = (const float*)d_in[3];
    const float* v0      = (const float*)d_in[4];
    const void*  src_mask = d_in[5];
    const void*  notdone  = d_in[6];
    const float* main_w  = (const float*)d_in[7];
    const float* main_b  = (const float*)d_in[8];
    const float* proj_w  = (const float*)d_in[9];
    const float* proj_b  = (const float*)d_in[10];
    const float* out_w   = (const float*)d_in[11];
    const float* out_b   = (const float*)d_in[12];
    const float* ln_w    = (const float*)d_in[13];
    const float* ln_b    = (const float*)d_in[14];
    const float* pos_w   = (const float*)d_in[15];
    const float* pos_b   = (const float*)d_in[16];
    float* out = (float*)d_out;

    cudaFuncSetAttribute(conv_fused_kernel,
                         cudaFuncAttributeMaxDynamicSharedMemorySize, CONV_SMEM);

    detect_kernel<<<1, 256>>>((const int*)src_mask);
    bias_kernel<<<(BB * MEM + 255) / 256, 256>>>(src_mask, notdone);
    for (int n = 0; n < LNUM; n++) {
        int tot = BB * C_MAIN * PIX;
        prep_kernel<<<(tot + 255) / 256, 256>>>(x, h0, n, n == 0 ? 1 : 0);
        conv_fused_kernel<<<dim3(BB, 8), 256, CONV_SMEM>>>(main_w, main_b,
                                                           proj_w, proj_b, n);
        attn_kernel<<<dim3(BB, NHH), 256>>>(k0, v0, pos_w, pos_b, n);
        final_kernel<<<BB, 256>>>(out_w, out_b, ln_w, ln_b, c0, x, n,
                                  out, n == LNUM - 1 ? 1 : 0);
    }
}